// round 15
// baseline (speedup 1.0000x reference)
#include <cuda_runtime.h>
#include <cuda_bf16.h>
#include <cstdint>

#define NPIX 4096
#define CIN  512
#define B    4

__device__ __align__(16) __nv_bfloat16 g_q [(size_t)B * NPIX * 64];    // [b][n][d]
__device__ __align__(16) __nv_bfloat16 g_k [(size_t)B * NPIX * 64];    // [b][n][d]
__device__ __align__(16) __nv_bfloat16 g_v [(size_t)B * CIN * NPIX];   // [b][c][n]
__device__ __align__(16) __nv_bfloat16 g_wqk[128 * CIN];               // [q64;k64][c]
__device__ __align__(16) __nv_bfloat16 g_wv [CIN * CIN];               // [o][c]

// ------------------------------ helpers -----------------------------------
__device__ __forceinline__ uint32_t smem_u32(const void* p) {
    uint32_t a;
    asm("{ .reg .u64 t; cvta.to.shared.u64 t, %1; cvt.u32.u64 %0, t; }" : "=r"(a) : "l"(p));
    return a;
}
__device__ __forceinline__ void ldsm_x4(uint32_t* r, uint32_t a) {
    asm volatile("ldmatrix.sync.aligned.m8n8.x4.shared.b16 {%0,%1,%2,%3}, [%4];"
        : "=r"(r[0]), "=r"(r[1]), "=r"(r[2]), "=r"(r[3]) : "r"(a));
}
__device__ __forceinline__ void ldsm_x4t(uint32_t* r, uint32_t a) {
    asm volatile("ldmatrix.sync.aligned.m8n8.x4.trans.shared.b16 {%0,%1,%2,%3}, [%4];"
        : "=r"(r[0]), "=r"(r[1]), "=r"(r[2]), "=r"(r[3]) : "r"(a));
}
__device__ __forceinline__ void mma_bf16(float* d, const uint32_t* a, const uint32_t* b) {
    asm volatile("mma.sync.aligned.m16n8k16.row.col.f32.bf16.bf16.f32 "
        "{%0,%1,%2,%3},{%4,%5,%6,%7},{%8,%9},{%0,%1,%2,%3};"
        : "+f"(d[0]), "+f"(d[1]), "+f"(d[2]), "+f"(d[3])
        : "r"(a[0]), "r"(a[1]), "r"(a[2]), "r"(a[3]), "r"(b[0]), "r"(b[1]));
}
__device__ __forceinline__ void cp16(uint32_t dst, const void* src) {
    asm volatile("cp.async.cg.shared.global [%0], [%1], 16;" :: "r"(dst), "l"(src));
}
#define CP_COMMIT() asm volatile("cp.async.commit_group;" ::: "memory")
#define CP_WAIT0()  asm volatile("cp.async.wait_group 0;" ::: "memory")
#define STS32(a,v) asm volatile("st.shared.b32 [%0], %1;" :: "r"(a),"r"(v) : "memory")
__device__ __forceinline__ uint32_t pack_bf2(float lo, float hi) {
    uint32_t u;
    asm("cvt.rn.bf16x2.f32 %0, %1, %2;" : "=r"(u) : "f"(hi), "f"(lo));
    return u;
}

// -------------------------- weight convert ---------------------------------
__global__ void convert_w_kernel(const float* __restrict__ Wq, const float* __restrict__ Wk,
                                 const float* __restrict__ Wv) {
    int i = blockIdx.x * 256 + threadIdx.x;
    if (i < 64 * CIN) g_wqk[i] = __float2bfloat16(Wq[i]);
    else if (i < 128 * CIN) g_wqk[i] = __float2bfloat16(Wk[i - 64 * CIN]);
    else if (i < 128 * CIN + CIN * CIN) g_wv[i - 128 * CIN] = __float2bfloat16(Wv[i - 128 * CIN]);
}

// ------------- fused proj (no xT): C[out(128), n(128)] = W . x -------------
__global__ __launch_bounds__(256)
void proj_qkv_kernel(const float* __restrict__ x, const float* __restrict__ bq,
                     const float* __restrict__ bk, const float* __restrict__ bv) {
    extern __shared__ char dsm[];
    const uint32_t sb = smem_u32(dsm);
    const uint32_t SW = sb, SX = sb + 36864;
    const int tid = threadIdx.x, wid = tid >> 5, lane = tid & 31;
    const int n0 = blockIdx.x * 128, chunk = blockIdx.y, b = blockIdx.z;
    const __nv_bfloat16* gW = (chunk == 0) ? g_wqk : (g_wv + (size_t)(chunk - 1) * 128 * CIN);
    const float* gx = x + (size_t)b * CIN * NPIX + n0;

    auto ldW = [&](uint32_t dst, int kk) {
        for (int i = tid; i < 1024; i += 256) {
            int r = i >> 3, s = i & 7;
            cp16(dst + r * 144 + s * 16, gW + (size_t)r * CIN + kk * 64 + s * 8);
        }
    };
    const int cl = tid >> 5, n2 = (tid & 31) * 2;
    auto ldx_regs = [&](uint32_t* r, int kk) {
        #pragma unroll
        for (int cp = 0; cp < 8; cp++) {
            const float* row = gx + (size_t)(kk * 64 + cl + cp * 8) * NPIX;
            #pragma unroll
            for (int np = 0; np < 2; np++) {
                float2 v = *reinterpret_cast<const float2*>(row + n2 + np * 64);
                r[cp * 2 + np] = pack_bf2(v.x, v.y);
            }
        }
    };
    auto stx = [&](uint32_t dstb, const uint32_t* r) {
        #pragma unroll
        for (int cp = 0; cp < 8; cp++)
            #pragma unroll
            for (int np = 0; np < 2; np++)
                STS32(dstb + (cl + cp * 8) * 272 + (n2 + np * 64) * 2, r[cp * 2 + np]);
    };

    uint32_t xr[16];
    ldW(SW, 0); CP_COMMIT();
    ldx_regs(xr, 0); stx(SX, xr);
    CP_WAIT0(); __syncthreads();

    const int ar = (lane & 7) + ((lane >> 3) & 1) * 8, ak = ((lane >> 4) & 1) * 8;
    const int vn = ((lane >> 3) & 1) * 8 + (lane & 7), vc = ((lane >> 4) & 1) * 8;
    float o[16][4] = {};

    for (int kk = 0; kk < 8; kk++) {
        const int buf = kk & 1;
        if (kk < 7) { ldW(SW + (buf ^ 1) * 18432, kk + 1); CP_COMMIT(); ldx_regs(xr, kk + 1); }
        const uint32_t Ab = SW + buf * 18432 + (16 * wid + ar) * 144 + ak * 2;
        const uint32_t Xb = SX + buf * 17408;
        uint32_t wa[4][4];
        #pragma unroll
        for (int kc = 0; kc < 4; kc++) ldsm_x4(wa[kc], Ab + kc * 32);
        #pragma unroll
        for (int nt = 0; nt < 8; nt++) {
            #pragma unroll
            for (int kc = 0; kc < 4; kc++) {
                uint32_t br[4];
                ldsm_x4t(br, Xb + (kc * 16 + vn) * 272 + (nt * 16 + vc) * 2);
                mma_bf16(o[nt * 2],     wa[kc], br);
                mma_bf16(o[nt * 2 + 1], wa[kc], br + 2);
            }
        }
        if (kk < 7) { stx(SX + (buf ^ 1) * 17408, xr); CP_WAIT0(); }
        __syncthreads();
    }

    const int r0 = 16 * wid + (lane >> 2);
    if (chunk == 0) {
        float* epi = reinterpret_cast<float*>(dsm);
        const float bb0 = (r0 < 64) ? __ldg(bq + r0) : __ldg(bk + r0 - 64);
        const float bb1 = (r0 + 8 < 64) ? __ldg(bq + r0 + 8) : __ldg(bk + r0 + 8 - 64);
        #pragma unroll
        for (int ot = 0; ot < 16; ot++) {
            int n = ot * 8 + (lane & 3) * 2;
            epi[r0 * 129 + n]           = o[ot][0] + bb0;
            epi[r0 * 129 + n + 1]       = o[ot][1] + bb0;
            epi[(r0 + 8) * 129 + n]     = o[ot][2] + bb1;
            epi[(r0 + 8) * 129 + n + 1] = o[ot][3] + bb1;
        }
        __syncthreads();
        for (int i = tid; i < 8192; i += 256) {
            int n = i >> 6, d2 = (i & 63) * 2;
            uint32_t pk = pack_bf2(epi[d2 * 129 + n], epi[(d2 + 1) * 129 + n]);
            __nv_bfloat16* base = (d2 < 64) ? g_q : g_k;
            *reinterpret_cast<uint32_t*>(base + ((size_t)b * NPIX + n0 + n) * 64 + (d2 & 63)) = pk;
        }
    } else {
        const int c0 = (chunk - 1) * 128;
        const float bb0 = __ldg(bv + c0 + r0), bb1 = __ldg(bv + c0 + r0 + 8);
        #pragma unroll
        for (int ot = 0; ot < 16; ot++) {
            int n = ot * 8 + (lane & 3) * 2;
            *reinterpret_cast<uint32_t*>(g_v + ((size_t)b * CIN + c0 + r0) * NPIX + n0 + n) =
                pack_bf2(o[ot][0] + bb0, o[ot][1] + bb0);
            *reinterpret_cast<uint32_t*>(g_v + ((size_t)b * CIN + c0 + r0 + 8) * NPIX + n0 + n) =
                pack_bf2(o[ot][2] + bb1, o[ot][3] + bb1);
        }
    }
}

// --------------------------- fused attention ------------------------------
// CTA 64m x 256c-half x b (grid 64x2x4), 128 threads = 4 warps arranged as
// 2 m-slots (32m) x 2 c-slots (128c). Each warp: 2 independent m-tiles,
// o[2][16][4] = 128 f32 regs; V fragments shared across both m-tiles
// (V crossbar traffic halved vs R7); S duplicated x2 within CTA.
// smem 90 KB: [SQK1 9216 | SK0 9216 | SV 2x36864]; 2 CTAs/SM.
// Epilogue reuses smem as f32 epi[64][257].
__global__ __launch_bounds__(128, 2)
void attn_kernel(const float* __restrict__ x, float* __restrict__ out) {
    extern __shared__ char dsm[];
    const uint32_t sb = smem_u32(dsm);
    const uint32_t SQK1 = sb, SK0 = sb + 9216, SV = sb + 18432;
    const int tid = threadIdx.x, wid = tid >> 5, lane = tid & 31;
    const int mslot = wid & 1, cw = wid >> 1;
    const int m0 = blockIdx.x * 64, chalf = blockIdx.y, b = blockIdx.z;

    const __nv_bfloat16* gQ = g_q + ((size_t)b * NPIX + m0) * 64;
    const __nv_bfloat16* gK = g_k + (size_t)b * NPIX * 64;
    const __nv_bfloat16* gV = g_v + ((size_t)b * CIN + chalf * 256) * NPIX;

    auto ldK = [&](uint32_t dst, int jj) {
        const __nv_bfloat16* src = gK + (size_t)jj * 64 * 64;
        for (int i = tid; i < 512; i += 128) {
            int r = i >> 3, s = i & 7;
            cp16(dst + r * 144 + s * 16, src + (size_t)r * 64 + s * 8);
        }
    };
    auto ldV = [&](uint32_t dst, int jj) {
        const __nv_bfloat16* src = gV + (size_t)jj * 64;   // [c][n]: row stride NPIX
        for (int i = tid; i < 2048; i += 128) {
            int r = i >> 3, s = i & 7;
            cp16(dst + r * 144 + s * 16, src + (size_t)r * NPIX + s * 8);
        }
    };
    // prologue: Q (64m x 64d into SQK1), K0, V0
    for (int i = tid; i < 512; i += 128) {
        int r = i >> 3, s = i & 7;
        cp16(SQK1 + r * 144 + s * 16, gQ + (size_t)r * 64 + s * 8);
    }
    ldK(SK0, 0); ldV(SV, 0);
    CP_COMMIT(); CP_WAIT0(); __syncthreads();

    const int ar = (lane & 7) + ((lane >> 3) & 1) * 8, ak = ((lane >> 4) & 1) * 8;
    const int bn = ((lane >> 4) & 1) * 8 + (lane & 7), bk2 = ((lane >> 3) & 1) * 8;

    // hoist Q fragments for both m-tiles; Q smem becomes K buffer 1
    uint32_t qa[2][4][4];
    #pragma unroll
    for (int mt = 0; mt < 2; mt++) {
        const uint32_t Ab = SQK1 + (mslot * 32 + mt * 16 + ar) * 144 + ak * 2;
        #pragma unroll
        for (int kc = 0; kc < 4; kc++) ldsm_x4(qa[mt][kc], Ab + kc * 32);
    }
    __syncthreads();

    float o[2][16][4] = {};
    float rs[2][2] = {};

    for (int j = 0; j < 64; j++) {
        const int buf = j & 1;
        const uint32_t Kb = buf ? SQK1 : SK0;
        const uint32_t Vb = SV + buf * 36864;
        if (j < 63) {
            ldK(buf ? SK0 : SQK1, j + 1);
            ldV(SV + (buf ^ 1) * 36864, j + 1);
            CP_COMMIT();
        }
        #pragma unroll
        for (int nt = 0; nt < 4; nt++) {
            // S = Q.K^T for both m-tiles (K fragments shared)
            float s[2][8] = {};
            #pragma unroll
            for (int kc = 0; kc < 4; kc++) {
                uint32_t br[4];
                ldsm_x4(br, Kb + (nt * 16 + bn) * 144 + (kc * 16 + bk2) * 2);
                #pragma unroll
                for (int mt = 0; mt < 2; mt++) {
                    mma_bf16(s[mt],     qa[mt][kc], br);
                    mma_bf16(s[mt] + 4, qa[mt][kc], br + 2);
                }
            }
            // exp + rowsum + pack (per m-tile)
            uint32_t pa[2][4];
            #pragma unroll
            for (int mt = 0; mt < 2; mt++) {
                #pragma unroll
                for (int t = 0; t < 8; t++) s[mt][t] = __expf(s[mt][t]);
                rs[mt][0] += s[mt][0] + s[mt][1] + s[mt][4] + s[mt][5];
                rs[mt][1] += s[mt][2] + s[mt][3] + s[mt][6] + s[mt][7];
                pa[mt][0] = pack_bf2(s[mt][0], s[mt][1]);
                pa[mt][1] = pack_bf2(s[mt][2], s[mt][3]);
                pa[mt][2] = pack_bf2(s[mt][4], s[mt][5]);
                pa[mt][3] = pack_bf2(s[mt][6], s[mt][7]);
            }
            // O += P.V^T over this warp's 128-c slice; V frag shared across mt
            #pragma unroll
            for (int ct = 0; ct < 8; ct++) {
                uint32_t vfr[4];
                ldsm_x4(vfr, Vb + (cw * 128 + ct * 16 + bn) * 144 + (nt * 16 + bk2) * 2);
                #pragma unroll
                for (int mt = 0; mt < 2; mt++) {
                    mma_bf16(o[mt][ct * 2],     pa[mt], vfr);
                    mma_bf16(o[mt][ct * 2 + 1], pa[mt], vfr + 2);
                }
            }
        }
        if (j < 63) CP_WAIT0();
        __syncthreads();
    }

    // quad-lane rowsum reduce (S computed fully per warp -> warp-local sums)
    float inv[2][2];
    #pragma unroll
    for (int mt = 0; mt < 2; mt++)
        #pragma unroll
        for (int h = 0; h < 2; h++) {
            float r = rs[mt][h];
            r += __shfl_xor_sync(0xffffffffu, r, 1);
            r += __shfl_xor_sync(0xffffffffu, r, 2);
            inv[mt][h] = 1.0f / r;
        }

    // epilogue: transpose through smem, out[b][c][m] = O/sum + x
    float* epi = reinterpret_cast<float*>(dsm);
    #pragma unroll
    for (int mt = 0; mt < 2; mt++) {
        const int r0 = mslot * 32 + mt * 16 + (lane >> 2);
        #pragma unroll
        for (int ot = 0; ot < 16; ot++) {
            int c = cw * 128 + ot * 8 + (lane & 3) * 2;
            epi[r0 * 257 + c]           = o[mt][ot][0] * inv[mt][0];
            epi[r0 * 257 + c + 1]       = o[mt][ot][1] * inv[mt][0];
            epi[(r0 + 8) * 257 + c]     = o[mt][ot][2] * inv[mt][1];
            epi[(r0 + 8) * 257 + c + 1] = o[mt][ot][3] * inv[mt][1];
        }
    }
    __syncthreads();
    const float* xb = x + (size_t)b * CIN * NPIX;
    float* ob = out + (size_t)b * CIN * NPIX;
    for (int i = tid; i < 256 * 64; i += 128) {
        int c = i >> 6, m = i & 63;
        size_t gidx = (size_t)(chalf * 256 + c) * NPIX + m0 + m;
        ob[gidx] = epi[m * 257 + c] + xb[gidx];
    }
}

// ---------------------------------------------------------------------------
extern "C" void kernel_launch(void* const* d_in, const int* in_sizes, int n_in,
                              void* d_out, int out_size)
{
    const float* x  = (const float*)d_in[0];
    const float* Wq = (const float*)d_in[1];
    const float* bq = (const float*)d_in[2];
    const float* Wk = (const float*)d_in[3];
    const float* bk = (const float*)d_in[4];
    const float* Wv = (const float*)d_in[5];
    const float* bv = (const float*)d_in[6];
    float* out = (float*)d_out;

    cudaFuncSetAttribute(proj_qkv_kernel, cudaFuncAttributeMaxDynamicSharedMemorySize, 71680);
    cudaFuncSetAttribute(attn_kernel,     cudaFuncAttributeMaxDynamicSharedMemorySize, 92160);

    convert_w_kernel<<<1280, 256>>>(Wq, Wk, Wv);
    proj_qkv_kernel<<<dim3(NPIX / 128, 5, B), 256, 71680>>>(x, bq, bk, bv);
    attn_kernel<<<dim3(NPIX / 64, 2, B), 128, 92160>>>(x, out);
}

// round 16
// speedup vs baseline: 1.3345x; 1.3345x over previous
#include <cuda_runtime.h>
#include <cuda_bf16.h>
#include <cstdint>

#define NPIX 4096
#define CIN  512
#define B    4

__device__ __align__(16) __nv_bfloat16 g_x [(size_t)B * CIN * NPIX];   // [b][c][n] bf16
__device__ __align__(16) __nv_bfloat16 g_q [(size_t)B * NPIX * 64];    // [b][n][d]
__device__ __align__(16) __nv_bfloat16 g_k [(size_t)B * NPIX * 64];    // [b][n][d]
__device__ __align__(16) __nv_bfloat16 g_v [(size_t)B * CIN * NPIX];   // [b][c][n]
__device__ __align__(16) __nv_bfloat16 g_wqk[128 * CIN];               // [q64;k64][c]
__device__ __align__(16) __nv_bfloat16 g_wv [CIN * CIN];               // [o][c]

// ------------------------------ helpers -----------------------------------
__device__ __forceinline__ uint32_t smem_u32(const void* p) {
    uint32_t a;
    asm("{ .reg .u64 t; cvta.to.shared.u64 t, %1; cvt.u32.u64 %0, t; }" : "=r"(a) : "l"(p));
    return a;
}
__device__ __forceinline__ void ldsm_x4(uint32_t* r, uint32_t a) {
    asm volatile("ldmatrix.sync.aligned.m8n8.x4.shared.b16 {%0,%1,%2,%3}, [%4];"
        : "=r"(r[0]), "=r"(r[1]), "=r"(r[2]), "=r"(r[3]) : "r"(a));
}
__device__ __forceinline__ void ldsm_x4t(uint32_t* r, uint32_t a) {
    asm volatile("ldmatrix.sync.aligned.m8n8.x4.trans.shared.b16 {%0,%1,%2,%3}, [%4];"
        : "=r"(r[0]), "=r"(r[1]), "=r"(r[2]), "=r"(r[3]) : "r"(a));
}
__device__ __forceinline__ void mma_bf16(float* d, const uint32_t* a, const uint32_t* b) {
    asm volatile("mma.sync.aligned.m16n8k16.row.col.f32.bf16.bf16.f32 "
        "{%0,%1,%2,%3},{%4,%5,%6,%7},{%8,%9},{%0,%1,%2,%3};"
        : "+f"(d[0]), "+f"(d[1]), "+f"(d[2]), "+f"(d[3])
        : "r"(a[0]), "r"(a[1]), "r"(a[2]), "r"(a[3]), "r"(b[0]), "r"(b[1]));
}
__device__ __forceinline__ void cp16(uint32_t dst, const void* src) {
    asm volatile("cp.async.cg.shared.global [%0], [%1], 16;" :: "r"(dst), "l"(src));
}
#define CP_COMMIT() asm volatile("cp.async.commit_group;" ::: "memory")
#define CP_WAIT0()  asm volatile("cp.async.wait_group 0;" ::: "memory")
__device__ __forceinline__ uint32_t pack_bf2(float lo, float hi) {
    uint32_t u;
    asm("cvt.rn.bf16x2.f32 %0, %1, %2;" : "=r"(u) : "f"(hi), "f"(lo));
    return u;
}

// -------------------------- converts ---------------------------------------
__global__ void convert_w_kernel(const float* __restrict__ Wq, const float* __restrict__ Wk,
                                 const float* __restrict__ Wv) {
    int i = blockIdx.x * 256 + threadIdx.x;
    if (i < 64 * CIN) g_wqk[i] = __float2bfloat16(Wq[i]);
    else if (i < 128 * CIN) g_wqk[i] = __float2bfloat16(Wk[i - 64 * CIN]);
    else if (i < 128 * CIN + CIN * CIN) g_wv[i - 128 * CIN] = __float2bfloat16(Wv[i - 128 * CIN]);
}

// x fp32 [b][c][n] -> bf16 same layout (pure streaming)
__global__ __launch_bounds__(256)
void convert_x_kernel(const float* __restrict__ x) {
    size_t i = ((size_t)blockIdx.x * 256 + threadIdx.x) * 4;
    float4 v = *reinterpret_cast<const float4*>(x + i);
    uint32_t lo = pack_bf2(v.x, v.y), hi = pack_bf2(v.z, v.w);
    *reinterpret_cast<uint2*>(g_x + i) = make_uint2(lo, hi);
}

// ------------- fused proj: C[out(128), n(128)] = W . x ---------------------
// A = W[out][c] (K-major, non-trans ldsm), B = g_x bf16 [c][n] (trans ldsm).
// chunk 0 -> q|k (transposed epilogue via smem), chunks 1-4 -> v[b][c][n].
// smem: W 2x18432 | X 2x17408 (= 71680); chunk0 epilogue reuses as f32[128][129].
__global__ __launch_bounds__(256)
void proj_qkv_kernel(const float* __restrict__ bq, const float* __restrict__ bk,
                     const float* __restrict__ bv) {
    extern __shared__ char dsm[];
    const uint32_t sb = smem_u32(dsm);
    const uint32_t SW = sb, SX = sb + 36864;
    const int tid = threadIdx.x, wid = tid >> 5, lane = tid & 31;
    const int n0 = blockIdx.x * 128, chunk = blockIdx.y, b = blockIdx.z;
    const __nv_bfloat16* gW = (chunk == 0) ? g_wqk : (g_wv + (size_t)(chunk - 1) * 128 * CIN);
    const __nv_bfloat16* gx = g_x + (size_t)b * CIN * NPIX + n0;

    auto ldW = [&](uint32_t dst, int kk) {
        for (int i = tid; i < 1024; i += 256) {
            int r = i >> 3, s = i & 7;
            cp16(dst + r * 144 + s * 16, gW + (size_t)r * CIN + kk * 64 + s * 8);
        }
    };
    // x chunk: 64 c-rows x 128 n bf16 -> smem [c][n], pitch 272
    auto ldX = [&](uint32_t dst, int kk) {
        for (int i = tid; i < 1024; i += 256) {
            int r = i >> 4, s = i & 15;
            cp16(dst + r * 272 + s * 16, gx + (size_t)(kk * 64 + r) * NPIX + s * 8);
        }
    };

    ldW(SW, 0); ldX(SX, 0); CP_COMMIT(); CP_WAIT0(); __syncthreads();

    const int ar = (lane & 7) + ((lane >> 3) & 1) * 8, ak = ((lane >> 4) & 1) * 8;
    const int vn = ((lane >> 3) & 1) * 8 + (lane & 7), vc = ((lane >> 4) & 1) * 8;
    float o[16][4] = {};

    for (int kk = 0; kk < 8; kk++) {
        const int buf = kk & 1;
        if (kk < 7) {
            ldW(SW + (buf ^ 1) * 18432, kk + 1);
            ldX(SX + (buf ^ 1) * 17408, kk + 1);
            CP_COMMIT();
        }
        const uint32_t Ab = SW + buf * 18432 + (16 * wid + ar) * 144 + ak * 2;
        const uint32_t Xb = SX + buf * 17408;
        uint32_t wa[4][4];
        #pragma unroll
        for (int kc = 0; kc < 4; kc++) ldsm_x4(wa[kc], Ab + kc * 32);
        #pragma unroll
        for (int nt = 0; nt < 8; nt++) {
            #pragma unroll
            for (int kc = 0; kc < 4; kc++) {
                uint32_t br[4];
                ldsm_x4t(br, Xb + (kc * 16 + vn) * 272 + (nt * 16 + vc) * 2);
                mma_bf16(o[nt * 2],     wa[kc], br);
                mma_bf16(o[nt * 2 + 1], wa[kc], br + 2);
            }
        }
        if (kk < 7) CP_WAIT0();
        __syncthreads();
    }

    const int r0 = 16 * wid + (lane >> 2);
    if (chunk == 0) {
        float* epi = reinterpret_cast<float*>(dsm);
        const float bb0 = (r0 < 64) ? __ldg(bq + r0) : __ldg(bk + r0 - 64);
        const float bb1 = (r0 + 8 < 64) ? __ldg(bq + r0 + 8) : __ldg(bk + r0 + 8 - 64);
        #pragma unroll
        for (int ot = 0; ot < 16; ot++) {
            int n = ot * 8 + (lane & 3) * 2;
            epi[r0 * 129 + n]           = o[ot][0] + bb0;
            epi[r0 * 129 + n + 1]       = o[ot][1] + bb0;
            epi[(r0 + 8) * 129 + n]     = o[ot][2] + bb1;
            epi[(r0 + 8) * 129 + n + 1] = o[ot][3] + bb1;
        }
        __syncthreads();
        for (int i = tid; i < 8192; i += 256) {
            int n = i >> 6, d2 = (i & 63) * 2;
            uint32_t pk = pack_bf2(epi[d2 * 129 + n], epi[(d2 + 1) * 129 + n]);
            __nv_bfloat16* base = (d2 < 64) ? g_q : g_k;
            *reinterpret_cast<uint32_t*>(base + ((size_t)b * NPIX + n0 + n) * 64 + (d2 & 63)) = pk;
        }
    } else {
        const int c0 = (chunk - 1) * 128;
        const float bb0 = __ldg(bv + c0 + r0), bb1 = __ldg(bv + c0 + r0 + 8);
        #pragma unroll
        for (int ot = 0; ot < 16; ot++) {
            int n = ot * 8 + (lane & 3) * 2;
            *reinterpret_cast<uint32_t*>(g_v + ((size_t)b * CIN + c0 + r0) * NPIX + n0 + n) =
                pack_bf2(o[ot][0] + bb0, o[ot][1] + bb0);
            *reinterpret_cast<uint32_t*>(g_v + ((size_t)b * CIN + c0 + r0 + 8) * NPIX + n0 + n) =
                pack_bf2(o[ot][2] + bb1, o[ot][3] + bb1);
        }
    }
}

// --------------------------- fused attention (R13 engine, unchanged) -------
// CTA 64m x 256c-half x b (grid 64x2x4), 128 threads = 4 warps,
// each 16m x 256c, n-tile 64, 2 CTAs/SM. V [b][c][n] -> tile [256c][64n]
// pitch 144, non-trans ldsm. smem 90 KB:
// [SQK1 9216 | SK0 9216 | SV 2x36864]; Q smem recycled as K buf 1.
// Epilogue reuses smem as f32 epi[64][257].
__global__ __launch_bounds__(128, 2)
void attn_kernel(const float* __restrict__ x, float* __restrict__ out) {
    extern __shared__ char dsm[];
    const uint32_t sb = smem_u32(dsm);
    const uint32_t SQK1 = sb, SK0 = sb + 9216, SV = sb + 18432;
    const int tid = threadIdx.x, wid = tid >> 5, lane = tid & 31;
    const int m0 = blockIdx.x * 64, chalf = blockIdx.y, b = blockIdx.z;

    const __nv_bfloat16* gQ = g_q + ((size_t)b * NPIX + m0) * 64;
    const __nv_bfloat16* gK = g_k + (size_t)b * NPIX * 64;
    const __nv_bfloat16* gV = g_v + ((size_t)b * CIN + chalf * 256) * NPIX;

    auto ldK = [&](uint32_t dst, int jj) {
        const __nv_bfloat16* src = gK + (size_t)jj * 64 * 64;
        for (int i = tid; i < 512; i += 128) {
            int r = i >> 3, s = i & 7;
            cp16(dst + r * 144 + s * 16, src + (size_t)r * 64 + s * 8);
        }
    };
    auto ldV = [&](uint32_t dst, int jj) {
        const __nv_bfloat16* src = gV + (size_t)jj * 64;   // [c][n]: row stride NPIX
        for (int i = tid; i < 2048; i += 128) {
            int r = i >> 3, s = i & 7;
            cp16(dst + r * 144 + s * 16, src + (size_t)r * NPIX + s * 8);
        }
    };
    // prologue: Q (64m x 64d into SQK1), K0, V0
    for (int i = tid; i < 512; i += 128) {
        int r = i >> 3, s = i & 7;
        cp16(SQK1 + r * 144 + s * 16, gQ + (size_t)r * 64 + s * 8);
    }
    ldK(SK0, 0); ldV(SV, 0);
    CP_COMMIT(); CP_WAIT0(); __syncthreads();

    const int ar = (lane & 7) + ((lane >> 3) & 1) * 8, ak = ((lane >> 4) & 1) * 8;
    const int bn = ((lane >> 4) & 1) * 8 + (lane & 7), bk2 = ((lane >> 3) & 1) * 8;

    // hoist Q fragments; Q smem becomes K buffer 1
    uint32_t qa[4][4];
    {
        const uint32_t Ab = SQK1 + (wid * 16 + ar) * 144 + ak * 2;
        #pragma unroll
        for (int kc = 0; kc < 4; kc++) ldsm_x4(qa[kc], Ab + kc * 32);
    }
    __syncthreads();

    float o[32][4] = {};
    float rs[2] = {};

    for (int j = 0; j < 64; j++) {
        const int buf = j & 1;
        const uint32_t Kb = buf ? SQK1 : SK0;
        const uint32_t Vb = SV + buf * 36864;
        if (j < 63) {
            ldK(buf ? SK0 : SQK1, j + 1);
            ldV(SV + (buf ^ 1) * 36864, j + 1);
            CP_COMMIT();
        }
        #pragma unroll
        for (int nt = 0; nt < 4; nt++) {
            // S = Q.K^T (16m x 16n)
            float s[8] = {};
            #pragma unroll
            for (int kc = 0; kc < 4; kc++) {
                uint32_t br[4];
                ldsm_x4(br, Kb + (nt * 16 + bn) * 144 + (kc * 16 + bk2) * 2);
                mma_bf16(s,     qa[kc], br);
                mma_bf16(s + 4, qa[kc], br + 2);
            }
            // exp + rowsum + pack
            #pragma unroll
            for (int t = 0; t < 8; t++) s[t] = __expf(s[t]);
            rs[0] += s[0] + s[1] + s[4] + s[5];
            rs[1] += s[2] + s[3] + s[6] + s[7];
            uint32_t pa[4];
            pa[0] = pack_bf2(s[0], s[1]);
            pa[1] = pack_bf2(s[2], s[3]);
            pa[2] = pack_bf2(s[4], s[5]);
            pa[3] = pack_bf2(s[6], s[7]);
            // O += P.V^T over 256 c; V tile [c][n] pitch 144, non-trans
            #pragma unroll
            for (int ct = 0; ct < 16; ct++) {
                uint32_t vfr[4];
                ldsm_x4(vfr, Vb + (ct * 16 + bn) * 144 + (nt * 16 + bk2) * 2);
                mma_bf16(o[ct * 2],     pa, vfr);
                mma_bf16(o[ct * 2 + 1], pa, vfr + 2);
            }
        }
        if (j < 63) CP_WAIT0();
        __syncthreads();
    }

    // quad-lane rowsum reduce
    float inv[2];
    #pragma unroll
    for (int h = 0; h < 2; h++) {
        float r = rs[h];
        r += __shfl_xor_sync(0xffffffffu, r, 1);
        r += __shfl_xor_sync(0xffffffffu, r, 2);
        inv[h] = 1.0f / r;
    }

    // epilogue: transpose through smem, out[b][c][m] = O/sum + x
    float* epi = reinterpret_cast<float*>(dsm);
    const int r0 = wid * 16 + (lane >> 2);
    #pragma unroll
    for (int ot = 0; ot < 32; ot++) {
        int c = ot * 8 + (lane & 3) * 2;
        epi[r0 * 257 + c]           = o[ot][0] * inv[0];
        epi[r0 * 257 + c + 1]       = o[ot][1] * inv[0];
        epi[(r0 + 8) * 257 + c]     = o[ot][2] * inv[1];
        epi[(r0 + 8) * 257 + c + 1] = o[ot][3] * inv[1];
    }
    __syncthreads();
    const float* xb = x + (size_t)b * CIN * NPIX;
    float* ob = out + (size_t)b * CIN * NPIX;
    for (int i = tid; i < 256 * 64; i += 128) {
        int c = i >> 6, m = i & 63;
        size_t gidx = (size_t)(chalf * 256 + c) * NPIX + m0 + m;
        ob[gidx] = epi[m * 257 + c] + xb[gidx];
    }
}

// ---------------------------------------------------------------------------
extern "C" void kernel_launch(void* const* d_in, const int* in_sizes, int n_in,
                              void* d_out, int out_size)
{
    const float* x  = (const float*)d_in[0];
    const float* Wq = (const float*)d_in[1];
    const float* bq = (const float*)d_in[2];
    const float* Wk = (const float*)d_in[3];
    const float* bk = (const float*)d_in[4];
    const float* Wv = (const float*)d_in[5];
    const float* bv = (const float*)d_in[6];
    float* out = (float*)d_out;

    cudaFuncSetAttribute(proj_qkv_kernel, cudaFuncAttributeMaxDynamicSharedMemorySize, 71680);
    cudaFuncSetAttribute(attn_kernel,     cudaFuncAttributeMaxDynamicSharedMemorySize, 92160);

    convert_w_kernel<<<1280, 256>>>(Wq, Wk, Wv);
    convert_x_kernel<<<(B * CIN * NPIX) / (256 * 4), 256>>>(x);
    proj_qkv_kernel<<<dim3(NPIX / 128, 5, B), 256, 71680>>>(bq, bk, bv);
    attn_kernel<<<dim3(NPIX / 64, 2, B), 128, 92160>>>(x, out);
}

// round 17
// speedup vs baseline: 1.3682x; 1.0253x over previous
#include <cuda_runtime.h>
#include <cuda_bf16.h>
#include <cstdint>

#define NPIX 4096
#define CIN  512
#define B    4

__device__ __align__(16) __nv_bfloat16 g_q [(size_t)B * NPIX * 64];    // [b][n][d]
__device__ __align__(16) __nv_bfloat16 g_k [(size_t)B * NPIX * 64];    // [b][n][d]
__device__ __align__(16) __nv_bfloat16 g_v [(size_t)B * CIN * NPIX];   // [b][c][n]
__device__ __align__(16) __nv_bfloat16 g_wqk[128 * CIN];               // [q64;k64][c]
__device__ __align__(16) __nv_bfloat16 g_wv [CIN * CIN];               // [o][c]

// ------------------------------ helpers -----------------------------------
__device__ __forceinline__ uint32_t smem_u32(const void* p) {
    uint32_t a;
    asm("{ .reg .u64 t; cvta.to.shared.u64 t, %1; cvt.u32.u64 %0, t; }" : "=r"(a) : "l"(p));
    return a;
}
__device__ __forceinline__ void ldsm_x4(uint32_t* r, uint32_t a) {
    asm volatile("ldmatrix.sync.aligned.m8n8.x4.shared.b16 {%0,%1,%2,%3}, [%4];"
        : "=r"(r[0]), "=r"(r[1]), "=r"(r[2]), "=r"(r[3]) : "r"(a));
}
__device__ __forceinline__ void ldsm_x4t(uint32_t* r, uint32_t a) {
    asm volatile("ldmatrix.sync.aligned.m8n8.x4.trans.shared.b16 {%0,%1,%2,%3}, [%4];"
        : "=r"(r[0]), "=r"(r[1]), "=r"(r[2]), "=r"(r[3]) : "r"(a));
}
__device__ __forceinline__ void mma_bf16(float* d, const uint32_t* a, const uint32_t* b) {
    asm volatile("mma.sync.aligned.m16n8k16.row.col.f32.bf16.bf16.f32 "
        "{%0,%1,%2,%3},{%4,%5,%6,%7},{%8,%9},{%0,%1,%2,%3};"
        : "+f"(d[0]), "+f"(d[1]), "+f"(d[2]), "+f"(d[3])
        : "r"(a[0]), "r"(a[1]), "r"(a[2]), "r"(a[3]), "r"(b[0]), "r"(b[1]));
}
__device__ __forceinline__ void cp16(uint32_t dst, const void* src) {
    asm volatile("cp.async.cg.shared.global [%0], [%1], 16;" :: "r"(dst), "l"(src));
}
#define CP_COMMIT() asm volatile("cp.async.commit_group;" ::: "memory")
#define CP_WAIT0()  asm volatile("cp.async.wait_group 0;" ::: "memory")
#define STS32(a,v) asm volatile("st.shared.b32 [%0], %1;" :: "r"(a),"r"(v) : "memory")
__device__ __forceinline__ uint32_t pack_bf2(float lo, float hi) {
    uint32_t u;
    asm("cvt.rn.bf16x2.f32 %0, %1, %2;" : "=r"(u) : "f"(hi), "f"(lo));
    return u;
}

// -------------------------- weight convert ---------------------------------
__global__ void convert_w_kernel(const float* __restrict__ Wq, const float* __restrict__ Wk,
                                 const float* __restrict__ Wv) {
    int i = blockIdx.x * 256 + threadIdx.x;
    if (i < 64 * CIN) g_wqk[i] = __float2bfloat16(Wq[i]);
    else if (i < 128 * CIN) g_wqk[i] = __float2bfloat16(Wk[i - 64 * CIN]);
    else if (i < 128 * CIN + CIN * CIN) g_wv[i - 128 * CIN] = __float2bfloat16(Wv[i - 128 * CIN]);
}

// ------------- fused proj (R13): C[out(128), n(128)] = W . x ---------------
__global__ __launch_bounds__(256)
void proj_qkv_kernel(const float* __restrict__ x, const float* __restrict__ bq,
                     const float* __restrict__ bk, const float* __restrict__ bv) {
    extern __shared__ char dsm[];
    const uint32_t sb = smem_u32(dsm);
    const uint32_t SW = sb, SX = sb + 36864;
    const int tid = threadIdx.x, wid = tid >> 5, lane = tid & 31;
    const int n0 = blockIdx.x * 128, chunk = blockIdx.y, b = blockIdx.z;
    const __nv_bfloat16* gW = (chunk == 0) ? g_wqk : (g_wv + (size_t)(chunk - 1) * 128 * CIN);
    const float* gx = x + (size_t)b * CIN * NPIX + n0;

    auto ldW = [&](uint32_t dst, int kk) {
        for (int i = tid; i < 1024; i += 256) {
            int r = i >> 3, s = i & 7;
            cp16(dst + r * 144 + s * 16, gW + (size_t)r * CIN + kk * 64 + s * 8);
        }
    };
    const int cl = tid >> 5, n2 = (tid & 31) * 2;
    auto ldx_regs = [&](uint32_t* r, int kk) {
        #pragma unroll
        for (int cp = 0; cp < 8; cp++) {
            const float* row = gx + (size_t)(kk * 64 + cl + cp * 8) * NPIX;
            #pragma unroll
            for (int np = 0; np < 2; np++) {
                float2 v = *reinterpret_cast<const float2*>(row + n2 + np * 64);
                r[cp * 2 + np] = pack_bf2(v.x, v.y);
            }
        }
    };
    auto stx = [&](uint32_t dstb, const uint32_t* r) {
        #pragma unroll
        for (int cp = 0; cp < 8; cp++)
            #pragma unroll
            for (int np = 0; np < 2; np++)
                STS32(dstb + (cl + cp * 8) * 272 + (n2 + np * 64) * 2, r[cp * 2 + np]);
    };

    uint32_t xr[16];
    ldW(SW, 0); CP_COMMIT();
    ldx_regs(xr, 0); stx(SX, xr);
    CP_WAIT0(); __syncthreads();

    const int ar = (lane & 7) + ((lane >> 3) & 1) * 8, ak = ((lane >> 4) & 1) * 8;
    const int vn = ((lane >> 3) & 1) * 8 + (lane & 7), vc = ((lane >> 4) & 1) * 8;
    float o[16][4] = {};

    for (int kk = 0; kk < 8; kk++) {
        const int buf = kk & 1;
        if (kk < 7) { ldW(SW + (buf ^ 1) * 18432, kk + 1); CP_COMMIT(); ldx_regs(xr, kk + 1); }
        const uint32_t Ab = SW + buf * 18432 + (16 * wid + ar) * 144 + ak * 2;
        const uint32_t Xb = SX + buf * 17408;
        uint32_t wa[4][4];
        #pragma unroll
        for (int kc = 0; kc < 4; kc++) ldsm_x4(wa[kc], Ab + kc * 32);
        #pragma unroll
        for (int nt = 0; nt < 8; nt++) {
            #pragma unroll
            for (int kc = 0; kc < 4; kc++) {
                uint32_t br[4];
                ldsm_x4t(br, Xb + (kc * 16 + vn) * 272 + (nt * 16 + vc) * 2);
                mma_bf16(o[nt * 2],     wa[kc], br);
                mma_bf16(o[nt * 2 + 1], wa[kc], br + 2);
            }
        }
        if (kk < 7) { stx(SX + (buf ^ 1) * 17408, xr); CP_WAIT0(); }
        __syncthreads();
    }

    const int r0 = 16 * wid + (lane >> 2);
    if (chunk == 0) {
        float* epi = reinterpret_cast<float*>(dsm);
        const float bb0 = (r0 < 64) ? __ldg(bq + r0) : __ldg(bk + r0 - 64);
        const float bb1 = (r0 + 8 < 64) ? __ldg(bq + r0 + 8) : __ldg(bk + r0 + 8 - 64);
        #pragma unroll
        for (int ot = 0; ot < 16; ot++) {
            int n = ot * 8 + (lane & 3) * 2;
            epi[r0 * 129 + n]           = o[ot][0] + bb0;
            epi[r0 * 129 + n + 1]       = o[ot][1] + bb0;
            epi[(r0 + 8) * 129 + n]     = o[ot][2] + bb1;
            epi[(r0 + 8) * 129 + n + 1] = o[ot][3] + bb1;
        }
        __syncthreads();
        for (int i = tid; i < 8192; i += 256) {
            int n = i >> 6, d2 = (i & 63) * 2;
            uint32_t pk = pack_bf2(epi[d2 * 129 + n], epi[(d2 + 1) * 129 + n]);
            __nv_bfloat16* base = (d2 < 64) ? g_q : g_k;
            *reinterpret_cast<uint32_t*>(base + ((size_t)b * NPIX + n0 + n) * 64 + (d2 & 63)) = pk;
        }
    } else {
        const int c0 = (chunk - 1) * 128;
        const float bb0 = __ldg(bv + c0 + r0), bb1 = __ldg(bv + c0 + r0 + 8);
        #pragma unroll
        for (int ot = 0; ot < 16; ot++) {
            int n = ot * 8 + (lane & 3) * 2;
            *reinterpret_cast<uint32_t*>(g_v + ((size_t)b * CIN + c0 + r0) * NPIX + n0 + n) =
                pack_bf2(o[ot][0] + bb0, o[ot][1] + bb0);
            *reinterpret_cast<uint32_t*>(g_v + ((size_t)b * CIN + c0 + r0 + 8) * NPIX + n0 + n) =
                pack_bf2(o[ot][2] + bb1, o[ot][3] + bb1);
        }
    }
}

// --------------------------- fused attention ------------------------------
// R13 engine + software-pipelined S: per j-iter, S-MMAs for nt+1 are issued
// BEFORE exp/pack/O of nt (ping-pong s[2][8]) so MUFU + O-HMMA overlap the
// in-flight S-HMMA. CTA 64m x 256c-half x b, 4 warps of 16m x 256c, 2 CTAs/SM.
// smem 90 KB: [SQK1 9216 | SK0 9216 | SV 2x36864]; epilogue f32 epi[64][257].
__global__ __launch_bounds__(128, 2)
void attn_kernel(const float* __restrict__ x, float* __restrict__ out) {
    extern __shared__ char dsm[];
    const uint32_t sb = smem_u32(dsm);
    const uint32_t SQK1 = sb, SK0 = sb + 9216, SV = sb + 18432;
    const int tid = threadIdx.x, wid = tid >> 5, lane = tid & 31;
    const int m0 = blockIdx.x * 64, chalf = blockIdx.y, b = blockIdx.z;

    const __nv_bfloat16* gQ = g_q + ((size_t)b * NPIX + m0) * 64;
    const __nv_bfloat16* gK = g_k + (size_t)b * NPIX * 64;
    const __nv_bfloat16* gV = g_v + ((size_t)b * CIN + chalf * 256) * NPIX;

    auto ldK = [&](uint32_t dst, int jj) {
        const __nv_bfloat16* src = gK + (size_t)jj * 64 * 64;
        for (int i = tid; i < 512; i += 128) {
            int r = i >> 3, s = i & 7;
            cp16(dst + r * 144 + s * 16, src + (size_t)r * 64 + s * 8);
        }
    };
    auto ldV = [&](uint32_t dst, int jj) {
        const __nv_bfloat16* src = gV + (size_t)jj * 64;   // [c][n]: row stride NPIX
        for (int i = tid; i < 2048; i += 128) {
            int r = i >> 3, s = i & 7;
            cp16(dst + r * 144 + s * 16, src + (size_t)r * NPIX + s * 8);
        }
    };
    // prologue: Q (64m x 64d into SQK1), K0, V0
    for (int i = tid; i < 512; i += 128) {
        int r = i >> 3, s = i & 7;
        cp16(SQK1 + r * 144 + s * 16, gQ + (size_t)r * 64 + s * 8);
    }
    ldK(SK0, 0); ldV(SV, 0);
    CP_COMMIT(); CP_WAIT0(); __syncthreads();

    const int ar = (lane & 7) + ((lane >> 3) & 1) * 8, ak = ((lane >> 4) & 1) * 8;
    const int bn = ((lane >> 4) & 1) * 8 + (lane & 7), bk2 = ((lane >> 3) & 1) * 8;

    // hoist Q fragments; Q smem becomes K buffer 1
    uint32_t qa[4][4];
    {
        const uint32_t Ab = SQK1 + (wid * 16 + ar) * 144 + ak * 2;
        #pragma unroll
        for (int kc = 0; kc < 4; kc++) ldsm_x4(qa[kc], Ab + kc * 32);
    }
    __syncthreads();

    float o[32][4] = {};
    float rs[2] = {};

    for (int j = 0; j < 64; j++) {
        const int buf = j & 1;
        const uint32_t Kb = buf ? SQK1 : SK0;
        const uint32_t Vb = SV + buf * 36864;
        if (j < 63) {
            ldK(buf ? SK0 : SQK1, j + 1);
            ldV(SV + (buf ^ 1) * 36864, j + 1);
            CP_COMMIT();
        }
        // S block for one 16n chunk
        auto Sblk = [&](int nt, float* s) {
            #pragma unroll
            for (int t = 0; t < 8; t++) s[t] = 0.f;
            #pragma unroll
            for (int kc = 0; kc < 4; kc++) {
                uint32_t br[4];
                ldsm_x4(br, Kb + (nt * 16 + bn) * 144 + (kc * 16 + bk2) * 2);
                mma_bf16(s,     qa[kc], br);
                mma_bf16(s + 4, qa[kc], br + 2);
            }
        };

        float s[2][8];
        Sblk(0, s[0]);
        #pragma unroll
        for (int nt = 0; nt < 4; nt++) {
            float* sc = s[nt & 1];
            // issue next S before consuming current (overlaps exp/pack/O)
            if (nt < 3) Sblk(nt + 1, s[(nt & 1) ^ 1]);
            // exp + rowsum + pack for current
            #pragma unroll
            for (int t = 0; t < 8; t++) sc[t] = __expf(sc[t]);
            rs[0] += sc[0] + sc[1] + sc[4] + sc[5];
            rs[1] += sc[2] + sc[3] + sc[6] + sc[7];
            uint32_t pa[4];
            pa[0] = pack_bf2(sc[0], sc[1]);
            pa[1] = pack_bf2(sc[2], sc[3]);
            pa[2] = pack_bf2(sc[4], sc[5]);
            pa[3] = pack_bf2(sc[6], sc[7]);
            // O += P.V^T over 256 c; V tile [c][n] pitch 144, non-trans
            #pragma unroll
            for (int ct = 0; ct < 16; ct++) {
                uint32_t vfr[4];
                ldsm_x4(vfr, Vb + (ct * 16 + bn) * 144 + (nt * 16 + bk2) * 2);
                mma_bf16(o[ct * 2],     pa, vfr);
                mma_bf16(o[ct * 2 + 1], pa, vfr + 2);
            }
        }
        if (j < 63) CP_WAIT0();
        __syncthreads();
    }

    // quad-lane rowsum reduce
    float inv[2];
    #pragma unroll
    for (int h = 0; h < 2; h++) {
        float r = rs[h];
        r += __shfl_xor_sync(0xffffffffu, r, 1);
        r += __shfl_xor_sync(0xffffffffu, r, 2);
        inv[h] = 1.0f / r;
    }

    // epilogue: transpose through smem, out[b][c][m] = O/sum + x
    float* epi = reinterpret_cast<float*>(dsm);
    const int r0 = wid * 16 + (lane >> 2);
    #pragma unroll
    for (int ot = 0; ot < 32; ot++) {
        int c = ot * 8 + (lane & 3) * 2;
        epi[r0 * 257 + c]           = o[ot][0] * inv[0];
        epi[r0 * 257 + c + 1]       = o[ot][1] * inv[0];
        epi[(r0 + 8) * 257 + c]     = o[ot][2] * inv[1];
        epi[(r0 + 8) * 257 + c + 1] = o[ot][3] * inv[1];
    }
    __syncthreads();
    const float* xb = x + (size_t)b * CIN * NPIX;
    float* ob = out + (size_t)b * CIN * NPIX;
    for (int i = tid; i < 256 * 64; i += 128) {
        int c = i >> 6, m = i & 63;
        size_t gidx = (size_t)(chalf * 256 + c) * NPIX + m0 + m;
        ob[gidx] = epi[m * 257 + c] + xb[gidx];
    }
}

// ---------------------------------------------------------------------------
extern "C" void kernel_launch(void* const* d_in, const int* in_sizes, int n_in,
                              void* d_out, int out_size)
{
    const float* x  = (const float*)d_in[0];
    const float* Wq = (const float*)d_in[1];
    const float* bq = (const float*)d_in[2];
    const float* Wk = (const float*)d_in[3];
    const float* bk = (const float*)d_in[4];
    const float* Wv = (const float*)d_in[5];
    const float* bv = (const float*)d_in[6];
    float* out = (float*)d_out;

    cudaFuncSetAttribute(proj_qkv_kernel, cudaFuncAttributeMaxDynamicSharedMemorySize, 71680);
    cudaFuncSetAttribute(attn_kernel,     cudaFuncAttributeMaxDynamicSharedMemorySize, 92160);

    convert_w_kernel<<<1280, 256>>>(Wq, Wk, Wv);
    proj_qkv_kernel<<<dim3(NPIX / 128, 5, B), 256, 71680>>>(x, bq, bk, bv);
    attn_kernel<<<dim3(NPIX / 64, 2, B), 128, 92160>>>(x, out);
}